// round 6
// baseline (speedup 1.0000x reference)
#include <cuda_runtime.h>
#include <cuda_fp16.h>

#define MDIM  256
#define SKPAD 208

typedef unsigned long long ull;

// ---- packed fp32x2 helpers ----
__device__ __forceinline__ ull fma2(ull a, ull b, ull c) {
    ull d;
    asm("fma.rn.f32x2 %0, %1, %2, %3;" : "=l"(d) : "l"(a), "l"(b), "l"(c));
    return d;
}
__device__ __forceinline__ ull mul2(ull a, ull b) {
    ull d;
    asm("mul.rn.f32x2 %0, %1, %2;" : "=l"(d) : "l"(a), "l"(b));
    return d;
}
__device__ __forceinline__ ull add2(ull a, ull b) {
    ull d;
    asm("add.rn.f32x2 %0, %1, %2;" : "=l"(d) : "l"(a), "l"(b));
    return d;
}
__device__ __forceinline__ ull pack2(float x, float y) {
    ull r;
    asm("mov.b64 %0, {%1, %2};" : "=l"(r) : "f"(x), "f"(y));
    return r;
}
__device__ __forceinline__ float2 unpack2(ull a) {
    float2 f;
    asm("mov.b64 {%0, %1}, %2;" : "=f"(f.x), "=f"(f.y) : "l"(a));
    return f;
}
__device__ __forceinline__ ull h2f2(unsigned h) {
    ull r;
    asm("{\n\t.reg .b16 lo, hi;\n\t.reg .f32 flo, fhi;\n\t"
        "mov.b32 {lo, hi}, %1;\n\t"
        "cvt.f32.f16 flo, lo;\n\tcvt.f32.f16 fhi, hi;\n\t"
        "mov.b64 %0, {flo, fhi};\n\t}" : "=l"(r) : "r"(h));
    return r;
}

// ---------------------------------------------------------------------------
// Single fused kernel: per-batch W-projection + attention + output projection.
// 128 threads per CTA, one CTA per batch element, 7 CTAs/SM.
// ---------------------------------------------------------------------------
#define SA_BYTES   (SKPAD * 128)              // 26624: fp16 swizzled tile (aliased by partials)
#define SC_OFF     SA_BYTES                   // 3328: scores [sk][4] fp32
#define SW_OFF     (SC_OFF + 3328)            // 1024: W row (later ctx)
#define SQ_OFF     (SW_OFF + 1024)            // 256: q
#define QP_OFF     (SQ_OFF + 256)             // 256: q@Q
#define SINV_OFF   (QP_OFF + 256)             // 32
#define SMEM_BYTES (SINV_OFF + 32)            // 31520

extern __shared__ char s_raw[];

__global__ __launch_bounds__(128, 7) void k2_fused(
    const float* __restrict__ query, const float* __restrict__ Qm,
    const float* __restrict__ Km,   const float* __restrict__ act,
    const float* __restrict__ V,    float* __restrict__ out, int nsk) {

    char*  sab   = s_raw;
    float* scf   = (float*)(s_raw + SC_OFF);
    float* sw    = (float*)(s_raw + SW_OFF);
    float* sq    = (float*)(s_raw + SQ_OFF);
    float* qp    = (float*)(s_raw + QP_OFF);
    float* sinv  = (float*)(s_raw + SINV_OFF);
    float* partf = (float*)s_raw;             // aliases tile after ctx phase

    int b = blockIdx.x;
    int t = threadIdx.x;
    int c8 = t & 7;

    // ---- Stage 0: q row
    if (t < 64) sq[t] = query[(size_t)b * 64 + t];
    __syncthreads();

    // ---- Stage 1: qp[c] = sum_i q[i] * Q[i][c]   (threads 0..63)
    if (t < 64) {
        float a0 = 0.f;
#pragma unroll 8
        for (int i = 0; i < 64; i++)
            a0 += sq[i] * __ldg(Qm + i * 64 + t);
        qp[t] = a0;
    }
    __syncthreads();

    // ---- Stage 2: W[h*64+a] = (1/8) sum_j qp[h*16+j] * K[a][h*16+j]
#pragma unroll
    for (int rep = 0; rep < 2; rep++) {
        int m = t + rep * 128;
        int h = m >> 6, a = m & 63;
        const float4* K4 = (const float4*)(Km + a * 64 + h * 16);
        float4 k0 = __ldg(K4), k1 = __ldg(K4 + 1), k2 = __ldg(K4 + 2), k3 = __ldg(K4 + 3);
        const float4* q4 = (const float4*)(qp + h * 16);
        float4 qa = q4[0], qb = q4[1], qc = q4[2], qd = q4[3];
        float wv = qa.x * k0.x + qa.y * k0.y + qa.z * k0.z + qa.w * k0.w
                 + qb.x * k1.x + qb.y * k1.y + qb.z * k1.z + qb.w * k1.w
                 + qc.x * k2.x + qc.y * k2.y + qc.z * k2.z + qc.w * k2.w
                 + qd.x * k3.x + qd.y * k3.y + qd.z * k3.z + qd.w * k3.w;
        sw[m] = 0.125f * wv;
    }
    __syncthreads();

    // ---- W octet -> regs: w2[h][j] covers dims [c8*8, c8*8+8) of head h
    ull w2[4][4];
#pragma unroll
    for (int h = 0; h < 4; h++) {
        ulonglong2 p0 = *(const ulonglong2*)(sw + h * 64 + c8 * 8);
        ulonglong2 p1 = *(const ulonglong2*)(sw + h * 64 + c8 * 8 + 4);
        w2[h][0] = p0.x; w2[h][1] = p0.y; w2[h][2] = p1.x; w2[h][3] = p1.y;
    }

    // ---- Fused load + scores: thread handles octet c8 of rows sk = t>>3 + 16k.
    //      Scores computed in fp32 from registers; tile stored fp16 swizzled.
    {
        const float4* ga = (const float4*)(act + (size_t)b * nsk * 64);
        int ngroups = nsk * 8;
        int iters = (ngroups + 127) >> 7;
        for (int k = 0; k < iters; k++) {
            int g = t + (k << 7);
            bool active = g < ngroups;
            float4 fa = make_float4(0, 0, 0, 0), fb = fa;
            if (active) { fa = ga[2 * g]; fb = ga[2 * g + 1]; }
            ull d0 = pack2(fa.x, fa.y), d1 = pack2(fa.z, fa.w);
            ull d2 = pack2(fb.x, fb.y), d3 = pack2(fb.z, fb.w);
            float sh[4];
#pragma unroll
            for (int h = 0; h < 4; h++) {
                ull a = fma2(d0, w2[h][0], fma2(d1, w2[h][1],
                        fma2(d2, w2[h][2], mul2(d3, w2[h][3]))));
                float2 f = unpack2(a);
                sh[h] = f.x + f.y;
            }
#pragma unroll
            for (int o = 1; o <= 4; o <<= 1) {
#pragma unroll
                for (int h = 0; h < 4; h++)
                    sh[h] += __shfl_xor_sync(0xffffffffu, sh[h], o);
            }
            if (active) {
                __half2 h0 = __floats2half2_rn(fa.x, fa.y);
                __half2 h1 = __floats2half2_rn(fa.z, fa.w);
                __half2 h2 = __floats2half2_rn(fb.x, fb.y);
                __half2 h3 = __floats2half2_rn(fb.z, fb.w);
                uint4 pk;
                pk.x = *(const unsigned*)&h0;
                pk.y = *(const unsigned*)&h1;
                pk.z = *(const unsigned*)&h2;
                pk.w = *(const unsigned*)&h3;
                unsigned off = ((unsigned)g << 4) ^ ((((unsigned)g >> 3) & 7u) << 4);
                *(uint4*)(sab + off) = pk;
                if ((t & 7) == 0) {
                    int sk = g >> 3;
                    *(float4*)(scf + sk * 4) = make_float4(sh[0], sh[1], sh[2], sh[3]);
                }
            }
        }
    }
    __syncthreads();

    // ---- Softmax: warp wid handles head wid, scores cached in regs
    {
        int wid = t >> 5, lane = t & 31;
        float vals[7];
        float m = -1e30f;
#pragma unroll
        for (int r = 0; r < 7; r++) {
            int sk = lane + (r << 5);
            vals[r] = (sk < nsk) ? scf[sk * 4 + wid] : -1e30f;
            m = fmaxf(m, vals[r]);
        }
#pragma unroll
        for (int o = 16; o; o >>= 1) m = fmaxf(m, __shfl_xor_sync(0xffffffffu, m, o));
        float s = 0.f;
#pragma unroll
        for (int r = 0; r < 7; r++) {
            int sk = lane + (r << 5);
            if (sk < nsk) {
                float p = __expf(vals[r] - m);
                s += p;
                scf[sk * 4 + wid] = p;
            }
        }
#pragma unroll
        for (int o = 16; o; o >>= 1) s += __shfl_xor_sync(0xffffffffu, s, o);
        if (lane == 0) sinv[wid] = 1.f / s;
    }
    __syncthreads();

    // ---- ctx partials: thread = (sg = t>>3, c8), all 4 heads, tile read once
    ull acc[16];
    {
#pragma unroll
        for (int v = 0; v < 16; v++) acc[v] = 0ull;
        int sg = t >> 3;
        int chunk = (nsk + 15) >> 4;
        int sk0 = sg * chunk;
        int sk1 = sk0 + chunk; if (sk1 > nsk) sk1 = nsk;
        for (int sk = sk0; sk < sk1; sk++) {
            unsigned off = (unsigned)(sk * 128) |
                           ((((unsigned)sk & 7u) ^ (unsigned)c8) << 4);
            uint4 av = *(const uint4*)(sab + off);
            float4 p4 = *(const float4*)(scf + sk * 4);
            ull d0 = h2f2(av.x), d1 = h2f2(av.y), d2 = h2f2(av.z), d3 = h2f2(av.w);
            ull ph0 = pack2(p4.x, p4.x), ph1 = pack2(p4.y, p4.y);
            ull ph2 = pack2(p4.z, p4.z), ph3 = pack2(p4.w, p4.w);
            acc[0]  = fma2(ph0, d0, acc[0]);  acc[1]  = fma2(ph0, d1, acc[1]);
            acc[2]  = fma2(ph0, d2, acc[2]);  acc[3]  = fma2(ph0, d3, acc[3]);
            acc[4]  = fma2(ph1, d0, acc[4]);  acc[5]  = fma2(ph1, d1, acc[5]);
            acc[6]  = fma2(ph1, d2, acc[6]);  acc[7]  = fma2(ph1, d3, acc[7]);
            acc[8]  = fma2(ph2, d0, acc[8]);  acc[9]  = fma2(ph2, d1, acc[9]);
            acc[10] = fma2(ph2, d2, acc[10]); acc[11] = fma2(ph2, d3, acc[11]);
            acc[12] = fma2(ph3, d0, acc[12]); acc[13] = fma2(ph3, d1, acc[13]);
            acc[14] = fma2(ph3, d2, acc[14]); acc[15] = fma2(ph3, d3, acc[15]);
        }
#pragma unroll
        for (int v = 0; v < 16; v++) {
            acc[v] = add2(acc[v], __shfl_xor_sync(0xffffffffu, acc[v], 8));
            acc[v] = add2(acc[v], __shfl_xor_sync(0xffffffffu, acc[v], 16));
        }
    }
    __syncthreads();   // tile reads complete; safe to alias partials over tile

    if ((t & 24) == 0) {
        int w = t >> 5;
        ull* pw = (ull*)partf + w * 128 + c8 * 4;
#pragma unroll
        for (int h = 0; h < 4; h++)
#pragma unroll
            for (int p = 0; p < 4; p++)
                pw[h * 32 + p] = acc[h * 4 + p];
    }
    __syncthreads();

    // ---- combine partials -> normalized ctx into sw (W dead)
    {
        float r0 = partf[t]       + partf[256 + t]       + partf[512 + t]       + partf[768 + t];
        float r1 = partf[t + 128] + partf[256 + t + 128] + partf[512 + t + 128] + partf[768 + t + 128];
        sw[t]       = r0 * sinv[t >> 6];
        sw[t + 128] = r1 * sinv[(t + 128) >> 6];
    }
    __syncthreads();

    // ---- output projection: out[c] = sum_a ctx[h(c)*64+a] * V[a][c]
    if (t < 64) {
        int c = t, h = t >> 4;
        const ull* cx = (const ull*)(sw + h * 64);
        ull acc2 = 0ull;
#pragma unroll 8
        for (int a = 0; a < 32; a++) {
            float v0 = __ldg(V + (size_t)(2 * a) * 64 + c);
            float v1 = __ldg(V + (size_t)(2 * a + 1) * 64 + c);
            acc2 = fma2(cx[a], pack2(v0, v1), acc2);
        }
        float2 f = unpack2(acc2);
        out[(size_t)b * 64 + c] = f.x + f.y;
    }
}

// ---------------------------------------------------------------------------
extern "C" void kernel_launch(void* const* d_in, const int* in_sizes, int n_in,
                              void* d_out, int out_size) {
    const float* query = (const float*)d_in[0];   // [B,1,64]
    const float* act   = (const float*)d_in[1];   // [B,SK,64]
    const float* Q     = (const float*)d_in[2];   // [64,64]
    const float* K     = (const float*)d_in[3];   // [64,64]
    const float* V     = (const float*)d_in[4];   // [64,64]
    float* out = (float*)d_out;

    int B   = in_sizes[0] / 64;
    int nsk = in_sizes[1] / (B * 64);
    if (nsk > SKPAD) nsk = SKPAD;

    cudaFuncSetAttribute(k2_fused, cudaFuncAttributeMaxDynamicSharedMemorySize, SMEM_BYTES);

    k2_fused<<<B, 128, SMEM_BYTES>>>(query, Q, K, act, V, out, nsk);
}

// round 7
// speedup vs baseline: 1.0561x; 1.0561x over previous
#include <cuda_runtime.h>
#include <cuda_fp16.h>

#define SKPAD 208

typedef unsigned long long ull;

// ---- packed fp32x2 helpers ----
__device__ __forceinline__ ull fma2(ull a, ull b, ull c) {
    ull d;
    asm("fma.rn.f32x2 %0, %1, %2, %3;" : "=l"(d) : "l"(a), "l"(b), "l"(c));
    return d;
}
__device__ __forceinline__ ull add2(ull a, ull b) {
    ull d;
    asm("add.rn.f32x2 %0, %1, %2;" : "=l"(d) : "l"(a), "l"(b));
    return d;
}
__device__ __forceinline__ ull pack2(float x, float y) {
    ull r;
    asm("mov.b64 %0, {%1, %2};" : "=l"(r) : "f"(x), "f"(y));
    return r;
}
__device__ __forceinline__ float2 unpack2(ull a) {
    float2 f;
    asm("mov.b64 {%0, %1}, %2;" : "=f"(f.x), "=f"(f.y) : "l"(a));
    return f;
}
__device__ __forceinline__ ull h2f2(unsigned h) {
    ull r;
    asm("{\n\t.reg .b16 lo, hi;\n\t.reg .f32 flo, fhi;\n\t"
        "mov.b32 {lo, hi}, %1;\n\t"
        "cvt.f32.f16 flo, lo;\n\tcvt.f32.f16 fhi, hi;\n\t"
        "mov.b64 %0, {flo, fhi};\n\t}" : "=l"(r) : "r"(h));
    return r;
}

// ---------------------------------------------------------------------------
// Single fused kernel. 128 threads/CTA, one CTA per batch, 7 CTAs/SM.
// Stages: q -> qp=q@Q -> W=qp*K (in smem), then R5's attention phases A..F.
// ---------------------------------------------------------------------------
#define SA_BYTES   (SKPAD * 128)              // 26624: fp16 swizzled tile (aliased later)
#define SW_OFF     SA_BYTES                   // 1024: W row, later ctx
#define SC_OFF     (SW_OFF + 1024)            // 3328: packed scores ull[2][SKPAD]
#define SQ_OFF     (SC_OFF + 3328)            // 256: q
#define QP_OFF     (SQ_OFF + 256)             // 256: q@Q
#define SINV_OFF   (QP_OFF + 256)             // 32
#define SMEM_BYTES (SINV_OFF + 32)            // 31520

extern __shared__ char s_raw[];

__global__ __launch_bounds__(128, 7) void k2_fused(
    const float* __restrict__ query, const float* __restrict__ Qm,
    const float* __restrict__ Km,    const float* __restrict__ act,
    const float* __restrict__ V,     float* __restrict__ out, int nsk) {

    char*  sab   = s_raw;
    float* sw    = (float*)(s_raw + SW_OFF);
    ull*   scu   = (ull*)(s_raw + SC_OFF);
    float* sq    = (float*)(s_raw + SQ_OFF);
    float* qp    = (float*)(s_raw + QP_OFF);
    float* sinv  = (float*)(s_raw + SINV_OFF);
    float* partf = (float*)s_raw;             // aliases tile after ctx phase

    int b = blockIdx.x;
    int t = threadIdx.x;

    // ---- Stage 0: q row + Phase A: action tile -> fp16, XOR-swizzled
    if (t < 64) sq[t] = query[(size_t)b * 64 + t];
    {
        const float4* ga = (const float4*)(act + (size_t)b * nsk * 64);
        int ngroups = nsk * 8;
#pragma unroll 2
        for (int g = t; g < ngroups; g += 128) {
            float4 fa = ga[2 * g];
            float4 fb = ga[2 * g + 1];
            __half2 h0 = __floats2half2_rn(fa.x, fa.y);
            __half2 h1 = __floats2half2_rn(fa.z, fa.w);
            __half2 h2 = __floats2half2_rn(fb.x, fb.y);
            __half2 h3 = __floats2half2_rn(fb.z, fb.w);
            uint4 pk;
            pk.x = *(const unsigned*)&h0;
            pk.y = *(const unsigned*)&h1;
            pk.z = *(const unsigned*)&h2;
            pk.w = *(const unsigned*)&h3;
            unsigned off = ((unsigned)g << 4) ^ ((((unsigned)g >> 3) & 7u) << 4);
            *(uint4*)(sab + off) = pk;
        }
    }
    __syncthreads();

    // ---- Stage 1: qp[c] = sum_i q[i] * Q[i][c]  (threads 0..63)
    if (t < 64) {
        float a0 = 0.f;
#pragma unroll 8
        for (int i = 0; i < 64; i++)
            a0 += sq[i] * __ldg(Qm + i * 64 + t);
        qp[t] = a0;
    }
    __syncthreads();

    // ---- Stage 2: W[h*64+a] = (1/8) sum_j qp[h*16+j] * K[a][h*16+j]
#pragma unroll
    for (int rep = 0; rep < 2; rep++) {
        int m = t + rep * 128;
        int h = m >> 6, a = m & 63;
        const float4* K4 = (const float4*)(Km + a * 64 + h * 16);
        float4 k0 = __ldg(K4), k1 = __ldg(K4 + 1), k2 = __ldg(K4 + 2), k3 = __ldg(K4 + 3);
        const float4* q4 = (const float4*)(qp + h * 16);
        float4 qa = q4[0], qb = q4[1], qc = q4[2], qd = q4[3];
        float wv = qa.x * k0.x + qa.y * k0.y + qa.z * k0.z + qa.w * k0.w
                 + qb.x * k1.x + qb.y * k1.y + qb.z * k1.z + qb.w * k1.w
                 + qc.x * k2.x + qc.y * k2.y + qc.z * k2.z + qc.w * k2.w
                 + qd.x * k3.x + qd.y * k3.y + qd.z * k3.z + qd.w * k3.w;
        sw[m] = 0.125f * wv;
    }
    __syncthreads();

    // ---- Phase B: scores (f32x2). Thread t handles sk = t and sk = t + 128.
    {
        int sk1 = t, sk2 = t + 128;
        bool v2 = sk2 < nsk;
        if (sk1 < nsk) {
            unsigned swb1 = (unsigned)(sk1 * 128) | (((unsigned)sk1 & 7u) << 4);
            unsigned swb2 = (unsigned)(sk2 * 128) | (((unsigned)sk2 & 7u) << 4);
            ull a1[4] = {0, 0, 0, 0}, a2[4] = {0, 0, 0, 0};
#pragma unroll
            for (int i = 0; i < 8; i++) {
                uint4 av1 = *(const uint4*)(sab + (swb1 ^ ((unsigned)i << 4)));
                uint4 av2 = make_uint4(0, 0, 0, 0);
                if (v2) av2 = *(const uint4*)(sab + (swb2 ^ ((unsigned)i << 4)));
                ull d1[4] = {h2f2(av1.x), h2f2(av1.y), h2f2(av1.z), h2f2(av1.w)};
                ull d2[4] = {h2f2(av2.x), h2f2(av2.y), h2f2(av2.z), h2f2(av2.w)};
#pragma unroll
                for (int h = 0; h < 4; h++) {
                    ulonglong2 wA = *(const ulonglong2*)(sw + h * 64 + i * 8);
                    ulonglong2 wB = *(const ulonglong2*)(sw + h * 64 + i * 8 + 4);
                    a1[h] = fma2(d1[0], wA.x, a1[h]);
                    a1[h] = fma2(d1[1], wA.y, a1[h]);
                    a1[h] = fma2(d1[2], wB.x, a1[h]);
                    a1[h] = fma2(d1[3], wB.y, a1[h]);
                    a2[h] = fma2(d2[0], wA.x, a2[h]);
                    a2[h] = fma2(d2[1], wA.y, a2[h]);
                    a2[h] = fma2(d2[2], wB.x, a2[h]);
                    a2[h] = fma2(d2[3], wB.y, a2[h]);
                }
            }
            float s1[4], s2[4];
#pragma unroll
            for (int h = 0; h < 4; h++) {
                float2 f1 = unpack2(a1[h]); s1[h] = f1.x + f1.y;
                float2 f2 = unpack2(a2[h]); s2[h] = f2.x + f2.y;
            }
            scu[0 * SKPAD + sk1] = pack2(s1[0], s1[1]);
            scu[1 * SKPAD + sk1] = pack2(s1[2], s1[3]);
            if (v2) {
                scu[0 * SKPAD + sk2] = pack2(s2[0], s2[1]);
                scu[1 * SKPAD + sk2] = pack2(s2[2], s2[3]);
            }
        }
    }
    __syncthreads();

    // ---- Phase C: softmax, warps 0/1 = head pairs, scores cached in regs
    {
        int wid = t >> 5, lane = t & 31;
        if (wid < 2) {
            int base = wid * SKPAD;
            ull vals[7];
            float mx = -1e30f, my = -1e30f;
#pragma unroll
            for (int r = 0; r < 7; r++) {
                int sk = lane + r * 32;
                vals[r] = (sk < nsk) ? scu[base + sk] : pack2(-1e30f, -1e30f);
                float2 f = unpack2(vals[r]);
                mx = fmaxf(mx, f.x);
                my = fmaxf(my, f.y);
            }
#pragma unroll
            for (int o = 16; o; o >>= 1) {
                mx = fmaxf(mx, __shfl_xor_sync(0xffffffffu, mx, o));
                my = fmaxf(my, __shfl_xor_sync(0xffffffffu, my, o));
            }
            float sx = 0.f, sy = 0.f;
#pragma unroll
            for (int r = 0; r < 7; r++) {
                int sk = lane + r * 32;
                if (sk < nsk) {
                    float2 f = unpack2(vals[r]);
                    float px = __expf(f.x - mx);
                    float py = __expf(f.y - my);
                    sx += px; sy += py;
                    scu[base + sk] = pack2(px, py);
                }
            }
#pragma unroll
            for (int o = 16; o; o >>= 1) {
                sx += __shfl_xor_sync(0xffffffffu, sx, o);
                sy += __shfl_xor_sync(0xffffffffu, sy, o);
            }
            if (lane == 0) {
                sinv[wid * 2]     = 1.f / sx;
                sinv[wid * 2 + 1] = 1.f / sy;
            }
        }
    }
    __syncthreads();

    // ---- Phase D: ctx partials. 128 threads = 16 sk-groups x 8 dim-octets.
    ull acc[16];
    {
        int sg = t >> 3, c8 = t & 7;
#pragma unroll
        for (int v = 0; v < 16; v++) acc[v] = 0ull;
        int chunk = (nsk + 15) >> 4;
        int sk0 = sg * chunk;
        int sk1e = sk0 + chunk; if (sk1e > nsk) sk1e = nsk;
        for (int sk = sk0; sk < sk1e; sk++) {
            unsigned off = (unsigned)(sk * 128) |
                           ((((unsigned)sk & 7u) ^ (unsigned)c8) << 4);
            uint4 av = *(const uint4*)(sab + off);
            ull d0 = h2f2(av.x), d1 = h2f2(av.y), d2 = h2f2(av.z), d3 = h2f2(av.w);
            float2 p01 = unpack2(scu[sk]);
            float2 p23 = unpack2(scu[SKPAD + sk]);
            ull ph0 = pack2(p01.x, p01.x), ph1 = pack2(p01.y, p01.y);
            ull ph2 = pack2(p23.x, p23.x), ph3 = pack2(p23.y, p23.y);
            acc[0]  = fma2(ph0, d0, acc[0]);  acc[1]  = fma2(ph0, d1, acc[1]);
            acc[2]  = fma2(ph0, d2, acc[2]);  acc[3]  = fma2(ph0, d3, acc[3]);
            acc[4]  = fma2(ph1, d0, acc[4]);  acc[5]  = fma2(ph1, d1, acc[5]);
            acc[6]  = fma2(ph1, d2, acc[6]);  acc[7]  = fma2(ph1, d3, acc[7]);
            acc[8]  = fma2(ph2, d0, acc[8]);  acc[9]  = fma2(ph2, d1, acc[9]);
            acc[10] = fma2(ph2, d2, acc[10]); acc[11] = fma2(ph2, d3, acc[11]);
            acc[12] = fma2(ph3, d0, acc[12]); acc[13] = fma2(ph3, d1, acc[13]);
            acc[14] = fma2(ph3, d2, acc[14]); acc[15] = fma2(ph3, d3, acc[15]);
        }
#pragma unroll
        for (int v = 0; v < 16; v++) {
            acc[v] = add2(acc[v], __shfl_xor_sync(0xffffffffu, acc[v], 8));
            acc[v] = add2(acc[v], __shfl_xor_sync(0xffffffffu, acc[v], 16));
        }
    }
    __syncthreads();   // tile reads complete; alias partials over tile

    if ((t & 24) == 0) {
        int w = t >> 5, c8 = t & 7;
        ull* pw = (ull*)partf + w * 128 + c8 * 4;
#pragma unroll
        for (int h = 0; h < 4; h++)
#pragma unroll
            for (int p = 0; p < 4; p++)
                pw[h * 32 + p] = acc[h * 4 + p];
    }
    __syncthreads();

    // ---- Phase E: combine partials -> normalized ctx into sw
    {
        float r0 = partf[t]       + partf[256 + t]       + partf[512 + t]       + partf[768 + t];
        float r1 = partf[t + 128] + partf[256 + t + 128] + partf[512 + t + 128] + partf[768 + t + 128];
        sw[t]       = r0 * sinv[t >> 6];
        sw[t + 128] = r1 * sinv[(t + 128) >> 6];
    }
    __syncthreads();

    // ---- Phase F: out[c] = sum_a ctx[h(c)*64+a] * V[a][c]
    if (t < 64) {
        int c = t, h = t >> 4;
        const ull* cx = (const ull*)(sw + h * 64);
        ull acc2 = 0ull;
#pragma unroll 8
        for (int a = 0; a < 32; a++) {
            float v0 = __ldg(V + (size_t)(2 * a) * 64 + c);
            float v1 = __ldg(V + (size_t)(2 * a + 1) * 64 + c);
            acc2 = fma2(cx[a], pack2(v0, v1), acc2);
        }
        float2 f = unpack2(acc2);
        out[(size_t)b * 64 + c] = f.x + f.y;
    }
}

// ---------------------------------------------------------------------------
extern "C" void kernel_launch(void* const* d_in, const int* in_sizes, int n_in,
                              void* d_out, int out_size) {
    const float* query = (const float*)d_in[0];   // [B,1,64]
    const float* act   = (const float*)d_in[1];   // [B,SK,64]
    const float* Q     = (const float*)d_in[2];   // [64,64]
    const float* K     = (const float*)d_in[3];   // [64,64]
    const float* V     = (const float*)d_in[4];   // [64,64]
    float* out = (float*)d_out;

    int B   = in_sizes[0] / 64;
    int nsk = in_sizes[1] / (B * 64);
    if (nsk > SKPAD) nsk = SKPAD;

    cudaFuncSetAttribute(k2_fused, cudaFuncAttributeMaxDynamicSharedMemorySize, SMEM_BYTES);

    k2_fused<<<B, 128, SMEM_BYTES>>>(query, Q, K, act, V, out, nsk);
}

// round 8
// speedup vs baseline: 1.1187x; 1.0592x over previous
#include <cuda_runtime.h>
#include <cuda_fp16.h>

#define SKPAD 208

typedef unsigned long long ull;

// ---- packed fp32x2 helpers ----
__device__ __forceinline__ ull fma2(ull a, ull b, ull c) {
    ull d;
    asm("fma.rn.f32x2 %0, %1, %2, %3;" : "=l"(d) : "l"(a), "l"(b), "l"(c));
    return d;
}
__device__ __forceinline__ ull add2(ull a, ull b) {
    ull d;
    asm("add.rn.f32x2 %0, %1, %2;" : "=l"(d) : "l"(a), "l"(b));
    return d;
}
__device__ __forceinline__ ull pack2(float x, float y) {
    ull r;
    asm("mov.b64 %0, {%1, %2};" : "=l"(r) : "f"(x), "f"(y));
    return r;
}
__device__ __forceinline__ float2 unpack2(ull a) {
    float2 f;
    asm("mov.b64 {%0, %1}, %2;" : "=f"(f.x), "=f"(f.y) : "l"(a));
    return f;
}
__device__ __forceinline__ ull h2f2(unsigned h) {
    ull r;
    asm("{\n\t.reg .b16 lo, hi;\n\t.reg .f32 flo, fhi;\n\t"
        "mov.b32 {lo, hi}, %1;\n\t"
        "cvt.f32.f16 flo, lo;\n\tcvt.f32.f16 fhi, hi;\n\t"
        "mov.b64 %0, {flo, fhi};\n\t}" : "=l"(r) : "r"(h));
    return r;
}

// ---------------------------------------------------------------------------
// Single fused kernel, 128 thr/CTA, 1 CTA/batch, 7 CTAs/SM.
// Warp 0: q -> qp -> W (L2 traffic) CONCURRENT with warps 1-3: tile load (DRAM).
// Then R5's attention phases B..F.
// ---------------------------------------------------------------------------
#define SA_BYTES   (SKPAD * 128)              // 26624: fp16 swizzled tile (aliased later)
#define SW_OFF     SA_BYTES                   // 1024: W row, later ctx
#define SC_OFF     (SW_OFF + 1024)            // 3328: packed scores ull[2][SKPAD]
#define QP_OFF     (SC_OFF + 3328)            // 256: q@Q
#define SINV_OFF   (QP_OFF + 256)             // 32
#define SMEM_BYTES (SINV_OFF + 32)            // 31264

extern __shared__ char s_raw[];

__global__ __launch_bounds__(128, 7) void k2_fused(
    const float* __restrict__ query, const float* __restrict__ Qm,
    const float* __restrict__ Km,    const float* __restrict__ act,
    const float* __restrict__ V,     float* __restrict__ out, int nsk) {

    char*  sab   = s_raw;
    float* sw    = (float*)(s_raw + SW_OFF);
    ull*   scu   = (ull*)(s_raw + SC_OFF);
    float* qp    = (float*)(s_raw + QP_OFF);
    float* sinv  = (float*)(s_raw + SINV_OFF);
    float* partf = (float*)s_raw;             // aliases tile after ctx phase

    int b = blockIdx.x;
    int t = threadIdx.x;
    int wid = t >> 5, lane = t & 31;

    if (wid == 0) {
        // ======== Warp 0: W pipeline (L2-bound, overlaps tile DRAM load) ====
        // q broadcast regs
        float q0 = query[(size_t)b * 64 + lane];
        float q1 = query[(size_t)b * 64 + 32 + lane];
        // qp[c] = sum_i q[i] * Q[i][c], lane handles c = lane, lane+32
        float ac0 = 0.f, ac1 = 0.f;
#pragma unroll 8
        for (int i = 0; i < 32; i++) {
            float qi = __shfl_sync(0xffffffffu, q0, i);
            ac0 += qi * __ldg(Qm + i * 64 + lane);
            ac1 += qi * __ldg(Qm + i * 64 + 32 + lane);
        }
#pragma unroll 8
        for (int i = 0; i < 32; i++) {
            float qi = __shfl_sync(0xffffffffu, q1, i);
            ac0 += qi * __ldg(Qm + (32 + i) * 64 + lane);
            ac1 += qi * __ldg(Qm + (32 + i) * 64 + 32 + lane);
        }
        qp[lane] = ac0;
        qp[lane + 32] = ac1;
        __syncwarp();
        // W[m] = (1/8) sum_j qp[h*16+j] * K[a][h*16+j], m = lane + 32k
#pragma unroll 2
        for (int k = 0; k < 8; k++) {
            int m = lane + (k << 5);
            int h = m >> 6, a = m & 63;
            const float4* K4 = (const float4*)(Km + a * 64 + h * 16);
            float4 k0 = __ldg(K4), k1 = __ldg(K4 + 1),
                   k2 = __ldg(K4 + 2), k3 = __ldg(K4 + 3);
            const float4* q4 = (const float4*)(qp + h * 16);
            float4 qa = q4[0], qb = q4[1], qc = q4[2], qd = q4[3];
            float wv = qa.x * k0.x + qa.y * k0.y + qa.z * k0.z + qa.w * k0.w
                     + qb.x * k1.x + qb.y * k1.y + qb.z * k1.z + qb.w * k1.w
                     + qc.x * k2.x + qc.y * k2.y + qc.z * k2.z + qc.w * k2.w
                     + qd.x * k3.x + qd.y * k3.y + qd.z * k3.z + qd.w * k3.w;
            sw[m] = 0.125f * wv;
        }
    } else {
        // ======== Warps 1-3: action tile -> fp16, XOR-swizzled ====
        int wt = t - 32;                       // 0..95
        const float4* ga = (const float4*)(act + (size_t)b * nsk * 64);
        int ngroups = nsk * 8;
#pragma unroll 2
        for (int g = wt; g < ngroups; g += 96) {
            float4 fa = ga[2 * g];
            float4 fb = ga[2 * g + 1];
            __half2 h0 = __floats2half2_rn(fa.x, fa.y);
            __half2 h1 = __floats2half2_rn(fa.z, fa.w);
            __half2 h2 = __floats2half2_rn(fb.x, fb.y);
            __half2 h3 = __floats2half2_rn(fb.z, fb.w);
            uint4 pk;
            pk.x = *(const unsigned*)&h0;
            pk.y = *(const unsigned*)&h1;
            pk.z = *(const unsigned*)&h2;
            pk.w = *(const unsigned*)&h3;
            unsigned off = ((unsigned)g << 4) ^ ((((unsigned)g >> 3) & 7u) << 4);
            *(uint4*)(sab + off) = pk;
        }
    }
    __syncthreads();

    // ---- Phase B: scores (f32x2). Thread t handles sk = t and sk = t + 128.
    {
        int sk1 = t, sk2 = t + 128;
        bool v2 = sk2 < nsk;
        if (sk1 < nsk) {
            unsigned swb1 = (unsigned)(sk1 * 128) | (((unsigned)sk1 & 7u) << 4);
            unsigned swb2 = (unsigned)(sk2 * 128) | (((unsigned)sk2 & 7u) << 4);
            ull a1[4] = {0, 0, 0, 0}, a2[4] = {0, 0, 0, 0};
#pragma unroll
            for (int i = 0; i < 8; i++) {
                uint4 av1 = *(const uint4*)(sab + (swb1 ^ ((unsigned)i << 4)));
                uint4 av2 = make_uint4(0, 0, 0, 0);
                if (v2) av2 = *(const uint4*)(sab + (swb2 ^ ((unsigned)i << 4)));
                ull d1[4] = {h2f2(av1.x), h2f2(av1.y), h2f2(av1.z), h2f2(av1.w)};
                ull d2[4] = {h2f2(av2.x), h2f2(av2.y), h2f2(av2.z), h2f2(av2.w)};
#pragma unroll
                for (int h = 0; h < 4; h++) {
                    ulonglong2 wA = *(const ulonglong2*)(sw + h * 64 + i * 8);
                    ulonglong2 wB = *(const ulonglong2*)(sw + h * 64 + i * 8 + 4);
                    a1[h] = fma2(d1[0], wA.x, a1[h]);
                    a1[h] = fma2(d1[1], wA.y, a1[h]);
                    a1[h] = fma2(d1[2], wB.x, a1[h]);
                    a1[h] = fma2(d1[3], wB.y, a1[h]);
                    a2[h] = fma2(d2[0], wA.x, a2[h]);
                    a2[h] = fma2(d2[1], wA.y, a2[h]);
                    a2[h] = fma2(d2[2], wB.x, a2[h]);
                    a2[h] = fma2(d2[3], wB.y, a2[h]);
                }
            }
            float s1[4], s2[4];
#pragma unroll
            for (int h = 0; h < 4; h++) {
                float2 f1 = unpack2(a1[h]); s1[h] = f1.x + f1.y;
                float2 f2 = unpack2(a2[h]); s2[h] = f2.x + f2.y;
            }
            scu[0 * SKPAD + sk1] = pack2(s1[0], s1[1]);
            scu[1 * SKPAD + sk1] = pack2(s1[2], s1[3]);
            if (v2) {
                scu[0 * SKPAD + sk2] = pack2(s2[0], s2[1]);
                scu[1 * SKPAD + sk2] = pack2(s2[2], s2[3]);
            }
        }
    }
    __syncthreads();

    // ---- Phase C: softmax, warps 0/1 = head pairs, scores cached in regs
    if (wid < 2) {
        int base = wid * SKPAD;
        ull vals[7];
        float mx = -1e30f, my = -1e30f;
#pragma unroll
        for (int r = 0; r < 7; r++) {
            int sk = lane + r * 32;
            vals[r] = (sk < nsk) ? scu[base + sk] : pack2(-1e30f, -1e30f);
            float2 f = unpack2(vals[r]);
            mx = fmaxf(mx, f.x);
            my = fmaxf(my, f.y);
        }
#pragma unroll
        for (int o = 16; o; o >>= 1) {
            mx = fmaxf(mx, __shfl_xor_sync(0xffffffffu, mx, o));
            my = fmaxf(my, __shfl_xor_sync(0xffffffffu, my, o));
        }
        float sx = 0.f, sy = 0.f;
#pragma unroll
        for (int r = 0; r < 7; r++) {
            int sk = lane + r * 32;
            if (sk < nsk) {
                float2 f = unpack2(vals[r]);
                float px = __expf(f.x - mx);
                float py = __expf(f.y - my);
                sx += px; sy += py;
                scu[base + sk] = pack2(px, py);
            }
        }
#pragma unroll
        for (int o = 16; o; o >>= 1) {
            sx += __shfl_xor_sync(0xffffffffu, sx, o);
            sy += __shfl_xor_sync(0xffffffffu, sy, o);
        }
        if (lane == 0) {
            sinv[wid * 2]     = 1.f / sx;
            sinv[wid * 2 + 1] = 1.f / sy;
        }
    }
    __syncthreads();

    // ---- Phase D: ctx partials. 128 threads = 16 sk-groups x 8 dim-octets.
    ull acc[16];
    {
        int sg = t >> 3, c8 = t & 7;
#pragma unroll
        for (int v = 0; v < 16; v++) acc[v] = 0ull;
        int chunk = (nsk + 15) >> 4;
        int sk0 = sg * chunk;
        int sk1e = sk0 + chunk; if (sk1e > nsk) sk1e = nsk;
        for (int sk = sk0; sk < sk1e; sk++) {
            unsigned off = (unsigned)(sk * 128) |
                           ((((unsigned)sk & 7u) ^ (unsigned)c8) << 4);
            uint4 av = *(const uint4*)(sab + off);
            ull d0 = h2f2(av.x), d1 = h2f2(av.y), d2 = h2f2(av.z), d3 = h2f2(av.w);
            float2 p01 = unpack2(scu[sk]);
            float2 p23 = unpack2(scu[SKPAD + sk]);
            ull ph0 = pack2(p01.x, p01.x), ph1 = pack2(p01.y, p01.y);
            ull ph2 = pack2(p23.x, p23.x), ph3 = pack2(p23.y, p23.y);
            acc[0]  = fma2(ph0, d0, acc[0]);  acc[1]  = fma2(ph0, d1, acc[1]);
            acc[2]  = fma2(ph0, d2, acc[2]);  acc[3]  = fma2(ph0, d3, acc[3]);
            acc[4]  = fma2(ph1, d0, acc[4]);  acc[5]  = fma2(ph1, d1, acc[5]);
            acc[6]  = fma2(ph1, d2, acc[6]);  acc[7]  = fma2(ph1, d3, acc[7]);
            acc[8]  = fma2(ph2, d0, acc[8]);  acc[9]  = fma2(ph2, d1, acc[9]);
            acc[10] = fma2(ph2, d2, acc[10]); acc[11] = fma2(ph2, d3, acc[11]);
            acc[12] = fma2(ph3, d0, acc[12]); acc[13] = fma2(ph3, d1, acc[13]);
            acc[14] = fma2(ph3, d2, acc[14]); acc[15] = fma2(ph3, d3, acc[15]);
        }
#pragma unroll
        for (int v = 0; v < 16; v++) {
            acc[v] = add2(acc[v], __shfl_xor_sync(0xffffffffu, acc[v], 8));
            acc[v] = add2(acc[v], __shfl_xor_sync(0xffffffffu, acc[v], 16));
        }
    }
    __syncthreads();   // tile reads complete; alias partials over tile

    if ((t & 24) == 0) {
        int w = t >> 5, c8 = t & 7;
        ull* pw = (ull*)partf + w * 128 + c8 * 4;
#pragma unroll
        for (int h = 0; h < 4; h++)
#pragma unroll
            for (int p = 0; p < 4; p++)
                pw[h * 32 + p] = acc[h * 4 + p];
    }
    __syncthreads();

    // ---- Phase E: combine partials -> normalized ctx into sw
    {
        float r0 = partf[t]       + partf[256 + t]       + partf[512 + t]       + partf[768 + t];
        float r1 = partf[t + 128] + partf[256 + t + 128] + partf[512 + t + 128] + partf[768 + t + 128];
        sw[t]       = r0 * sinv[t >> 6];
        sw[t + 128] = r1 * sinv[(t + 128) >> 6];
    }
    __syncthreads();

    // ---- Phase F: out[c] = sum_a ctx[h(c)*64+a] * V[a][c]
    if (t < 64) {
        int c = t, h = t >> 4;
        const ull* cx = (const ull*)(sw + h * 64);
        ull acc2 = 0ull;
#pragma unroll 8
        for (int a = 0; a < 32; a++) {
            float v0 = __ldg(V + (size_t)(2 * a) * 64 + c);
            float v1 = __ldg(V + (size_t)(2 * a + 1) * 64 + c);
            acc2 = fma2(cx[a], pack2(v0, v1), acc2);
        }
        float2 f = unpack2(acc2);
        out[(size_t)b * 64 + c] = f.x + f.y;
    }
}

// ---------------------------------------------------------------------------
extern "C" void kernel_launch(void* const* d_in, const int* in_sizes, int n_in,
                              void* d_out, int out_size) {
    const float* query = (const float*)d_in[0];   // [B,1,64]
    const float* act   = (const float*)d_in[1];   // [B,SK,64]
    const float* Q     = (const float*)d_in[2];   // [64,64]
    const float* K     = (const float*)d_in[3];   // [64,64]
    const float* V     = (const float*)d_in[4];   // [64,64]
    float* out = (float*)d_out;

    int B   = in_sizes[0] / 64;
    int nsk = in_sizes[1] / (B * 64);
    if (nsk > SKPAD) nsk = SKPAD;

    cudaFuncSetAttribute(k2_fused, cudaFuncAttributeMaxDynamicSharedMemorySize, SMEM_BYTES);

    k2_fused<<<B, 128, SMEM_BYTES>>>(query, Q, K, act, V, out, nsk);
}

// round 9
// speedup vs baseline: 1.2724x; 1.1374x over previous
#include <cuda_runtime.h>
#include <cuda_fp16.h>

#define SKPAD 208
#define MDIM  256
#define BMAX  8192

__device__ float g_W[(size_t)BMAX * MDIM];   // 8 MB scratch

typedef unsigned long long ull;

// ---- packed fp32x2 helpers ----
__device__ __forceinline__ ull fma2(ull a, ull b, ull c) {
    ull d;
    asm("fma.rn.f32x2 %0, %1, %2, %3;" : "=l"(d) : "l"(a), "l"(b), "l"(c));
    return d;
}
__device__ __forceinline__ ull add2(ull a, ull b) {
    ull d;
    asm("add.rn.f32x2 %0, %1, %2;" : "=l"(d) : "l"(a), "l"(b));
    return d;
}
__device__ __forceinline__ ull pack2(float x, float y) {
    ull r;
    asm("mov.b64 %0, {%1, %2};" : "=l"(r) : "f"(x), "f"(y));
    return r;
}
__device__ __forceinline__ float2 unpack2(ull a) {
    float2 f;
    asm("mov.b64 {%0, %1}, %2;" : "=f"(f.x), "=f"(f.y) : "l"(a));
    return f;
}
__device__ __forceinline__ ull h2f2(unsigned h) {
    ull r;
    asm("{\n\t.reg .b16 lo, hi;\n\t.reg .f32 flo, fhi;\n\t"
        "mov.b32 {lo, hi}, %1;\n\t"
        "cvt.f32.f16 flo, lo;\n\tcvt.f32.f16 fhi, hi;\n\t"
        "mov.b64 %0, {flo, fhi};\n\t}" : "=l"(r) : "r"(h));
    return r;
}

// ---------------------------------------------------------------------------
// K1 (fat version): 64 batches per CTA, 128 CTAs total (1 per SM, 1 wave).
// W[b][h*64+a] = (1/8) sum_j (q_b@Q)[h*16+j] * K[a][h*16+j]
// ---------------------------------------------------------------------------
__global__ __launch_bounds__(256) void k1_w(const float* __restrict__ query,
                                            const float* __restrict__ Qm,
                                            const float* __restrict__ Km, int B) {
    __shared__ float sQ[64 * 64];     // Q[i][c], natural
    __shared__ float qs[64 * 64];     // query rows, batch-major
    __shared__ float sK[64 * 68];     // K rows, padded
    __shared__ float qp[64 * 64];     // (q@Q)[b][c]
    int b0 = blockIdx.x * 64, t = threadIdx.x;

    for (int idx = t; idx < 4096; idx += 256) {
        sQ[idx] = Qm[idx];
        sK[(idx >> 6) * 68 + (idx & 63)] = Km[idx];
        int bb = idx >> 6;
        qs[idx] = (b0 + bb < B) ? query[(size_t)(b0 + bb) * 64 + (idx & 63)] : 0.f;
    }
    __syncthreads();

    // qp: thread (bg = t>>6 -> 16 batches, c = t&63)
    {
        int bg = t >> 6, c = t & 63;
        float acc[16];
#pragma unroll
        for (int b = 0; b < 16; b++) acc[b] = 0.f;
#pragma unroll 4
        for (int i4 = 0; i4 < 16; i4++) {
            float q0 = sQ[(i4 * 4 + 0) * 64 + c];
            float q1 = sQ[(i4 * 4 + 1) * 64 + c];
            float q2 = sQ[(i4 * 4 + 2) * 64 + c];
            float q3 = sQ[(i4 * 4 + 3) * 64 + c];
#pragma unroll
            for (int b = 0; b < 16; b++) {
                float4 v = *(const float4*)(qs + (bg * 16 + b) * 64 + i4 * 4);
                acc[b] += v.x * q0 + v.y * q1 + v.z * q2 + v.w * q3;
            }
        }
#pragma unroll
        for (int b = 0; b < 16; b++)
            qp[(bg * 16 + b) * 64 + c] = acc[b];
    }
    __syncthreads();

    // W: thread t -> m = t (h = t>>6, a = t&63), loop 64 batches
    {
        int h = t >> 6, a = t & 63;
        const float4* K4 = (const float4*)(sK + a * 68 + h * 16);
        float4 k0 = K4[0], k1 = K4[1], k2 = K4[2], k3 = K4[3];
        int bmax = B - b0; if (bmax > 64) bmax = 64;
        for (int b = 0; b < bmax; b++) {
            const float4* q4 = (const float4*)(qp + b * 64 + h * 16);
            float4 qa = q4[0], qb = q4[1], qc = q4[2], qd = q4[3];
            float wv = qa.x * k0.x + qa.y * k0.y + qa.z * k0.z + qa.w * k0.w
                     + qb.x * k1.x + qb.y * k1.y + qb.z * k1.z + qb.w * k1.w
                     + qc.x * k2.x + qc.y * k2.y + qc.z * k2.z + qc.w * k2.w
                     + qd.x * k3.x + qd.y * k3.y + qd.z * k3.z + qd.w * k3.w;
            g_W[(size_t)(b0 + b) * MDIM + t] = 0.125f * wv;
        }
    }
}

// ---------------------------------------------------------------------------
// K2: R5's attention kernel verbatim. 128 thr/CTA, 1 CTA/batch, 7 CTAs/SM.
// ---------------------------------------------------------------------------
#define SA_BYTES   (SKPAD * 128)              // 26624: fp16 swizzled tile (aliased later)
#define SW_OFF     SA_BYTES                   // 1024: W row, later ctx
#define SC_OFF     (SW_OFF + 1024)            // 3328: packed scores ull[2][SKPAD]
#define SINV_OFF   (SC_OFF + 3328)            // 32
#define SMEM_BYTES (SINV_OFF + 32)            // 31008

extern __shared__ char s_raw[];

__global__ __launch_bounds__(128, 7) void k2_fused(const float* __restrict__ act,
                                                   const float* __restrict__ V,
                                                   float* __restrict__ out, int nsk) {
    char*  sab   = s_raw;
    float* sw    = (float*)(s_raw + SW_OFF);
    ull*   scu   = (ull*)(s_raw + SC_OFF);
    float* sinv  = (float*)(s_raw + SINV_OFF);
    float* partf = (float*)s_raw;             // aliases tile after ctx phase

    int b = blockIdx.x;
    int t = threadIdx.x;

    sw[t]       = g_W[(size_t)b * MDIM + t];
    sw[t + 128] = g_W[(size_t)b * MDIM + t + 128];

    // ---- Phase A: action tile -> fp16, XOR-swizzled 16B chunks
    {
        const float4* ga = (const float4*)(act + (size_t)b * nsk * 64);
        int ngroups = nsk * 8;
#pragma unroll 2
        for (int g = t; g < ngroups; g += 128) {
            float4 fa = ga[2 * g];
            float4 fb = ga[2 * g + 1];
            __half2 h0 = __floats2half2_rn(fa.x, fa.y);
            __half2 h1 = __floats2half2_rn(fa.z, fa.w);
            __half2 h2 = __floats2half2_rn(fb.x, fb.y);
            __half2 h3 = __floats2half2_rn(fb.z, fb.w);
            uint4 pk;
            pk.x = *(const unsigned*)&h0;
            pk.y = *(const unsigned*)&h1;
            pk.z = *(const unsigned*)&h2;
            pk.w = *(const unsigned*)&h3;
            unsigned off = ((unsigned)g << 4) ^ ((((unsigned)g >> 3) & 7u) << 4);
            *(uint4*)(sab + off) = pk;
        }
    }
    __syncthreads();

    // ---- Phase B: scores (f32x2). Thread t handles sk = t and sk = t + 128.
    {
        int sk1 = t, sk2 = t + 128;
        bool v2 = sk2 < nsk;
        if (sk1 < nsk) {
            unsigned swb1 = (unsigned)(sk1 * 128) | (((unsigned)sk1 & 7u) << 4);
            unsigned swb2 = (unsigned)(sk2 * 128) | (((unsigned)sk2 & 7u) << 4);
            ull a1[4] = {0, 0, 0, 0}, a2[4] = {0, 0, 0, 0};
#pragma unroll
            for (int i = 0; i < 8; i++) {
                uint4 av1 = *(const uint4*)(sab + (swb1 ^ ((unsigned)i << 4)));
                uint4 av2 = make_uint4(0, 0, 0, 0);
                if (v2) av2 = *(const uint4*)(sab + (swb2 ^ ((unsigned)i << 4)));
                ull d1[4] = {h2f2(av1.x), h2f2(av1.y), h2f2(av1.z), h2f2(av1.w)};
                ull d2[4] = {h2f2(av2.x), h2f2(av2.y), h2f2(av2.z), h2f2(av2.w)};
#pragma unroll
                for (int h = 0; h < 4; h++) {
                    ulonglong2 wA = *(const ulonglong2*)(sw + h * 64 + i * 8);
                    ulonglong2 wB = *(const ulonglong2*)(sw + h * 64 + i * 8 + 4);
                    a1[h] = fma2(d1[0], wA.x, a1[h]);
                    a1[h] = fma2(d1[1], wA.y, a1[h]);
                    a1[h] = fma2(d1[2], wB.x, a1[h]);
                    a1[h] = fma2(d1[3], wB.y, a1[h]);
                    a2[h] = fma2(d2[0], wA.x, a2[h]);
                    a2[h] = fma2(d2[1], wA.y, a2[h]);
                    a2[h] = fma2(d2[2], wB.x, a2[h]);
                    a2[h] = fma2(d2[3], wB.y, a2[h]);
                }
            }
            float s1[4], s2[4];
#pragma unroll
            for (int h = 0; h < 4; h++) {
                float2 f1 = unpack2(a1[h]); s1[h] = f1.x + f1.y;
                float2 f2 = unpack2(a2[h]); s2[h] = f2.x + f2.y;
            }
            scu[0 * SKPAD + sk1] = pack2(s1[0], s1[1]);
            scu[1 * SKPAD + sk1] = pack2(s1[2], s1[3]);
            if (v2) {
                scu[0 * SKPAD + sk2] = pack2(s2[0], s2[1]);
                scu[1 * SKPAD + sk2] = pack2(s2[2], s2[3]);
            }
        }
    }
    __syncthreads();

    // ---- Phase C: softmax, warps 0/1 = head pairs, scores cached in regs
    {
        int wid = t >> 5, lane = t & 31;
        if (wid < 2) {
            int base = wid * SKPAD;
            ull vals[7];
            float mx = -1e30f, my = -1e30f;
#pragma unroll
            for (int r = 0; r < 7; r++) {
                int sk = lane + r * 32;
                vals[r] = (sk < nsk) ? scu[base + sk] : pack2(-1e30f, -1e30f);
                float2 f = unpack2(vals[r]);
                mx = fmaxf(mx, f.x);
                my = fmaxf(my, f.y);
            }
#pragma unroll
            for (int o = 16; o; o >>= 1) {
                mx = fmaxf(mx, __shfl_xor_sync(0xffffffffu, mx, o));
                my = fmaxf(my, __shfl_xor_sync(0xffffffffu, my, o));
            }
            float sx = 0.f, sy = 0.f;
#pragma unroll
            for (int r = 0; r < 7; r++) {
                int sk = lane + r * 32;
                if (sk < nsk) {
                    float2 f = unpack2(vals[r]);
                    float px = __expf(f.x - mx);
                    float py = __expf(f.y - my);
                    sx += px; sy += py;
                    scu[base + sk] = pack2(px, py);
                }
            }
#pragma unroll
            for (int o = 16; o; o >>= 1) {
                sx += __shfl_xor_sync(0xffffffffu, sx, o);
                sy += __shfl_xor_sync(0xffffffffu, sy, o);
            }
            if (lane == 0) {
                sinv[wid * 2]     = 1.f / sx;
                sinv[wid * 2 + 1] = 1.f / sy;
            }
        }
    }
    __syncthreads();

    // ---- Phase D: ctx partials. 128 threads = 16 sk-groups x 8 dim-octets.
    ull acc[16];
    {
        int sg = t >> 3, c8 = t & 7;
#pragma unroll
        for (int v = 0; v < 16; v++) acc[v] = 0ull;
        int chunk = (nsk + 15) >> 4;
        int sk0 = sg * chunk;
        int sk1e = sk0 + chunk; if (sk1e > nsk) sk1e = nsk;
        for (int sk = sk0; sk < sk1e; sk++) {
            unsigned off = (unsigned)(sk * 128) |
                           ((((unsigned)sk & 7u) ^ (unsigned)c8) << 4);
            uint4 av = *(const uint4*)(sab + off);
            ull d0 = h2f2(av.x), d1 = h2f2(av.y), d2 = h2f2(av.z), d3 = h2f2(av.w);
            float2 p01 = unpack2(scu[sk]);
            float2 p23 = unpack2(scu[SKPAD + sk]);
            ull ph0 = pack2(p01.x, p01.x), ph1 = pack2(p01.y, p01.y);
            ull ph2 = pack2(p23.x, p23.x), ph3 = pack2(p23.y, p23.y);
            acc[0]  = fma2(ph0, d0, acc[0]);  acc[1]  = fma2(ph0, d1, acc[1]);
            acc[2]  = fma2(ph0, d2, acc[2]);  acc[3]  = fma2(ph0, d3, acc[3]);
            acc[4]  = fma2(ph1, d0, acc[4]);  acc[5]  = fma2(ph1, d1, acc[5]);
            acc[6]  = fma2(ph1, d2, acc[6]);  acc[7]  = fma2(ph1, d3, acc[7]);
            acc[8]  = fma2(ph2, d0, acc[8]);  acc[9]  = fma2(ph2, d1, acc[9]);
            acc[10] = fma2(ph2, d2, acc[10]); acc[11] = fma2(ph2, d3, acc[11]);
            acc[12] = fma2(ph3, d0, acc[12]); acc[13] = fma2(ph3, d1, acc[13]);
            acc[14] = fma2(ph3, d2, acc[14]); acc[15] = fma2(ph3, d3, acc[15]);
        }
#pragma unroll
        for (int v = 0; v < 16; v++) {
            acc[v] = add2(acc[v], __shfl_xor_sync(0xffffffffu, acc[v], 8));
            acc[v] = add2(acc[v], __shfl_xor_sync(0xffffffffu, acc[v], 16));
        }
    }
    __syncthreads();   // tile reads complete; alias partials over tile

    if ((t & 24) == 0) {
        int w = t >> 5, c8 = t & 7;
        ull* pw = (ull*)partf + w * 128 + c8 * 4;
#pragma unroll
        for (int h = 0; h < 4; h++)
#pragma unroll
            for (int p = 0; p < 4; p++)
                pw[h * 32 + p] = acc[h * 4 + p];
    }
    __syncthreads();

    // ---- Phase E: combine partials -> normalized ctx into sw
    {
        float r0 = partf[t]       + partf[256 + t]       + partf[512 + t]       + partf[768 + t];
        float r1 = partf[t + 128] + partf[256 + t + 128] + partf[512 + t + 128] + partf[768 + t + 128];
        sw[t]       = r0 * sinv[t >> 6];
        sw[t + 128] = r1 * sinv[(t + 128) >> 6];
    }
    __syncthreads();

    // ---- Phase F: out[c] = sum_a ctx[h(c)*64+a] * V[a][c]
    if (t < 64) {
        int c = t, h = t >> 4;
        const ull* cx = (const ull*)(sw + h * 64);
        ull acc2 = 0ull;
#pragma unroll 8
        for (int a = 0; a < 32; a++) {
            float v0 = __ldg(V + (size_t)(2 * a) * 64 + c);
            float v1 = __ldg(V + (size_t)(2 * a + 1) * 64 + c);
            acc2 = fma2(cx[a], pack2(v0, v1), acc2);
        }
        float2 f = unpack2(acc2);
        out[(size_t)b * 64 + c] = f.x + f.y;
    }
}

// ---------------------------------------------------------------------------
extern "C" void kernel_launch(void* const* d_in, const int* in_sizes, int n_in,
                              void* d_out, int out_size) {
    const float* query = (const float*)d_in[0];   // [B,1,64]
    const float* act   = (const float*)d_in[1];   // [B,SK,64]
    const float* Q     = (const float*)d_in[2];   // [64,64]
    const float* K     = (const float*)d_in[3];   // [64,64]
    const float* V     = (const float*)d_in[4];   // [64,64]
    float* out = (float*)d_out;

    int B   = in_sizes[0] / 64;
    int nsk = in_sizes[1] / (B * 64);
    if (nsk > SKPAD) nsk = SKPAD;

    cudaFuncSetAttribute(k2_fused, cudaFuncAttributeMaxDynamicSharedMemorySize, SMEM_BYTES);

    k1_w<<<(B + 63) / 64, 256>>>(query, Q, K, B);
    k2_fused<<<B, 128, SMEM_BYTES>>>(act, V, out, nsk);
}